// round 17
// baseline (speedup 1.0000x reference)
#include <cuda_runtime.h>
#include <cuda_bf16.h>
#include <math.h>

#define B_SZ   16
#define C_IN   64
#define HH     256
#define WW     256
#define CKK    576
#define FC_DIM 512
#define IMG_PIX (HH * WW)
#define N_IMG  (B_SZ * C_IN)
#define FOUT_ELEMS ((size_t)N_IMG * IMG_PIX)

// Partials (deterministic fixed-order summation)
__device__ float g_p1[64][B_SZ * CKK];  // layer1 partials per 8-i-chunk (ic0 includes b1)
__device__ float g_p2[72][B_SZ * CKK];  // layer2 partials per 8-i-chunk (ic0 includes b2)
__device__ float g_kw[B_SZ * CKK];      // softmaxed kernel weights

// ---------------------------------------------------------------------------
// Layer 1: 192 blocks = (jt 0..2) x (ic 0..63). Block: 192 threads.
// Tile W1 [8 x 192] (6KB smem, 2 float4 loads/thread) + Fc slice [16 x 8].
// ---------------------------------------------------------------------------
__global__ __launch_bounds__(192) void EKG_mlp1(
    const float* __restrict__ Fc,
    const float* __restrict__ W1, const float* __restrict__ b1)
{
    __shared__ float sw[8 * 192];     // 6KB weight tile
    __shared__ float sfc[16 * 8];     // 512B input slice

    const int jt = blockIdx.x;        // 0..2
    const int ic = blockIdx.y;        // 0..63
    const int i0 = ic * 8;
    const int tid = threadIdx.x;
    const int j  = jt * 192 + tid;

    {
        const float4* __restrict__ W1_4 = (const float4*)W1;
        float4* sw4 = (float4*)sw;
        #pragma unroll
        for (int q = tid; q < 8 * 48; q += 192) {
            const int r = q / 48, c = q % 48;
            sw4[r * 48 + c] = __ldg(W1_4 + (size_t)(i0 + r) * (CKK / 4) + jt * 48 + c);
        }
    }
    if (tid < 32) {
        const float4* __restrict__ Fc4 = (const float4*)Fc;
        float4* sfc4 = (float4*)sfc;
        const int b = tid >> 1, c = tid & 1;
        sfc4[b * 2 + c] = __ldg(Fc4 + b * (FC_DIM / 4) + ic * 2 + c);
    }
    __syncthreads();

    float acc[16];
    #pragma unroll
    for (int b = 0; b < 16; ++b) acc[b] = 0.f;
    #pragma unroll
    for (int il = 0; il < 8; ++il) {
        const float w = sw[il * 192 + tid];
        #pragma unroll
        for (int b = 0; b < 16; ++b)
            acc[b] = fmaf(sfc[b * 8 + il], w, acc[b]);
    }

    const float bias = (ic == 0) ? b1[j] : 0.0f;
    #pragma unroll
    for (int b = 0; b < 16; ++b)
        g_p1[ic][b * CKK + j] = acc[b] + bias;
}

// ---------------------------------------------------------------------------
// Layer 2: 216 blocks = (jt 0..2) x (ic 0..71). Same structure over W2.
// Input h = relu(sum of 64 layer-1 partials), fixed-order 4-chain tree.
// ---------------------------------------------------------------------------
__global__ __launch_bounds__(192) void EKG_mlp2(
    const float* __restrict__ W2, const float* __restrict__ b2)
{
    __shared__ float sw[8 * 192];
    __shared__ float sfc[16 * 8];

    const int jt = blockIdx.x;        // 0..2
    const int ic = blockIdx.y;        // 0..71
    const int i0 = ic * 8;
    const int tid = threadIdx.x;
    const int j  = jt * 192 + tid;

    {
        const float4* __restrict__ W2_4 = (const float4*)W2;
        float4* sw4 = (float4*)sw;
        #pragma unroll
        for (int q = tid; q < 8 * 48; q += 192) {
            const int r = q / 48, c = q % 48;
            sw4[r * 48 + c] = __ldg(W2_4 + (size_t)(i0 + r) * (CKK / 4) + jt * 48 + c);
        }
    }
    // h slice [16 x 8] = relu(sum of 64 partials), fixed order
    if (tid < 128) {
        const int b = tid >> 3, il = tid & 7;
        const int idx = b * CKK + i0 + il;
        float s0 = 0.f, s1 = 0.f, s2 = 0.f, s3 = 0.f;
        #pragma unroll
        for (int t = 0; t < 16; ++t) {
            s0 += g_p1[t][idx];
            s1 += g_p1[16 + t][idx];
            s2 += g_p1[32 + t][idx];
            s3 += g_p1[48 + t][idx];
        }
        sfc[tid] = fmaxf((s0 + s1) + (s2 + s3), 0.0f);
    }
    __syncthreads();

    float acc[16];
    #pragma unroll
    for (int b = 0; b < 16; ++b) acc[b] = 0.f;
    #pragma unroll
    for (int il = 0; il < 8; ++il) {
        const float w = sw[il * 192 + tid];
        #pragma unroll
        for (int b = 0; b < 16; ++b)
            acc[b] = fmaf(sfc[b * 8 + il], w, acc[b]);
    }

    const float bias = (ic == 0) ? b2[j] : 0.0f;
    #pragma unroll
    for (int b = 0; b < 16; ++b)
        g_p2[ic][b * CKK + j] = acc[b] + bias;
}

// ---------------------------------------------------------------------------
// Softmax over 576 (summing the 72 logit partials). grid 16, block 576.
// ---------------------------------------------------------------------------
__global__ __launch_bounds__(CKK) void EKG_softmax(
    float* __restrict__ kw_tail, int write_tail)
{
    __shared__ float red[32];
    __shared__ float bcast;
    const int b = blockIdx.x;
    const int j = threadIdx.x;
    const int lane = j & 31;
    const int wid  = j >> 5;
    const int idx  = b * CKK + j;

    float s0 = 0.f, s1 = 0.f, s2 = 0.f, s3 = 0.f;
    #pragma unroll
    for (int t = 0; t < 18; ++t) {
        s0 += g_p2[t][idx];
        s1 += g_p2[18 + t][idx];
        s2 += g_p2[36 + t][idx];
        s3 += g_p2[54 + t][idx];
    }
    const float logit = (s0 + s1) + (s2 + s3);

    float m = logit;
    #pragma unroll
    for (int o = 16; o > 0; o >>= 1)
        m = fmaxf(m, __shfl_xor_sync(0xffffffffu, m, o));
    if (lane == 0) red[wid] = m;
    __syncthreads();
    if (wid == 0) {
        float v = (lane < 18) ? red[lane] : -INFINITY;
        #pragma unroll
        for (int o = 16; o > 0; o >>= 1)
            v = fmaxf(v, __shfl_xor_sync(0xffffffffu, v, o));
        if (lane == 0) bcast = v;
    }
    __syncthreads();
    const float e = expf(logit - bcast);

    float s = e;
    #pragma unroll
    for (int o = 16; o > 0; o >>= 1)
        s += __shfl_xor_sync(0xffffffffu, s, o);
    __syncthreads();
    if (lane == 0) red[wid] = s;
    __syncthreads();
    if (wid == 0) {
        float v = (lane < 18) ? red[lane] : 0.0f;
        #pragma unroll
        for (int o = 16; o > 0; o >>= 1)
            v += __shfl_xor_sync(0xffffffffu, v, o);
        if (lane == 0) bcast = v;
    }
    __syncthreads();

    const float kw = e / bcast;
    g_kw[idx] = kw;
    if (write_tail) kw_tail[idx] = kw;
}

// ---------------------------------------------------------------------------
// Depthwise 3x3 conv, reflect pad, no smem (measured-best, unchanged).
// Block 256: tx 0..63 (float4 col group), ty 0..3 (8-row strip). Grid (8,1024).
// ---------------------------------------------------------------------------
#define ROWS_PER_BLOCK 32
#define ROWS_PER_THREAD 8

__device__ __forceinline__ void load_row6(
    const float* __restrict__ img, int gr, int tx, float* __restrict__ w)
{
    gr = (gr < 0) ? 1 : ((gr > HH - 1) ? (2 * HH - 2 - gr) : gr);
    const float* rowp = img + gr * WW;
    const float4 q = __ldg((const float4*)rowp + tx);
    w[1] = q.x; w[2] = q.y; w[3] = q.z; w[4] = q.w;
    w[0] = (tx == 0)      ? q.y : __ldg(rowp + 4 * tx - 1);
    w[5] = (tx == WW/4-1) ? q.z : __ldg(rowp + 4 * tx + 4);
}

__global__ __launch_bounds__(256) void EKG_conv_kernel(
    const float* __restrict__ Fd,
    float* __restrict__ out)
{
    const int bc   = blockIdx.y;
    const int tid  = threadIdx.x;
    const int tx   = tid & 63;
    const int ty   = tid >> 6;
    const int rbase = blockIdx.x * ROWS_PER_BLOCK + ty * ROWS_PER_THREAD;

    const float* __restrict__ img = Fd  + (size_t)bc * IMG_PIX;
    float*       __restrict__ o   = out + (size_t)bc * IMG_PIX;

    const float* kwp = g_kw + bc * 9;
    const float w00 = __ldg(kwp+0), w01 = __ldg(kwp+1), w02 = __ldg(kwp+2);
    const float w10 = __ldg(kwp+3), w11 = __ldg(kwp+4), w12 = __ldg(kwp+5);
    const float w20 = __ldg(kwp+6), w21 = __ldg(kwp+7), w22 = __ldg(kwp+8);

    float win[3][6];
    load_row6(img, rbase - 1, tx, win[0]);
    load_row6(img, rbase + 0, tx, win[1]);

    #pragma unroll
    for (int rr = 0; rr < ROWS_PER_THREAD; ++rr) {
        load_row6(img, rbase + rr + 1, tx, win[(rr + 2) % 3]);

        const float* T  = win[rr % 3];
        const float* M  = win[(rr + 1) % 3];
        const float* Bt = win[(rr + 2) % 3];

        float4 r;
        r.x = w00*T[0]; r.x = fmaf(w01,T[1],r.x); r.x = fmaf(w02,T[2],r.x);
        r.x = fmaf(w10,M[0],r.x); r.x = fmaf(w11,M[1],r.x); r.x = fmaf(w12,M[2],r.x);
        r.x = fmaf(w20,Bt[0],r.x); r.x = fmaf(w21,Bt[1],r.x); r.x = fmaf(w22,Bt[2],r.x);

        r.y = w00*T[1]; r.y = fmaf(w01,T[2],r.y); r.y = fmaf(w02,T[3],r.y);
        r.y = fmaf(w10,M[1],r.y); r.y = fmaf(w11,M[2],r.y); r.y = fmaf(w12,M[3],r.y);
        r.y = fmaf(w20,Bt[1],r.y); r.y = fmaf(w21,Bt[2],r.y); r.y = fmaf(w22,Bt[3],r.y);

        r.z = w00*T[2]; r.z = fmaf(w01,T[3],r.z); r.z = fmaf(w02,T[4],r.z);
        r.z = fmaf(w10,M[2],r.z); r.z = fmaf(w11,M[3],r.z); r.z = fmaf(w12,M[4],r.z);
        r.z = fmaf(w20,Bt[2],r.z); r.z = fmaf(w21,Bt[3],r.z); r.z = fmaf(w22,Bt[4],r.z);

        r.w = w00*T[3]; r.w = fmaf(w01,T[4],r.w); r.w = fmaf(w02,T[5],r.w);
        r.w = fmaf(w10,M[3],r.w); r.w = fmaf(w11,M[4],r.w); r.w = fmaf(w12,M[5],r.w);
        r.w = fmaf(w20,Bt[3],r.w); r.w = fmaf(w21,Bt[4],r.w); r.w = fmaf(w22,Bt[5],r.w);

        __stcs((float4*)(o + (size_t)(rbase + rr) * WW + 4 * tx), r);
    }
}

// ---------------------------------------------------------------------------
extern "C" void kernel_launch(void* const* d_in, const int* in_sizes, int n_in,
                              void* d_out, int out_size) {
    const float* Fd = (const float*)d_in[0];
    const float* Fc = (const float*)d_in[1];
    const float* W1 = (const float*)d_in[2];
    const float* b1 = (const float*)d_in[3];
    const float* W2 = (const float*)d_in[4];
    const float* b2 = (const float*)d_in[5];
    float* out = (float*)d_out;

    const int write_tail = ((size_t)out_size >= FOUT_ELEMS + (size_t)B_SZ * CKK) ? 1 : 0;
    float* kw_tail = out + FOUT_ELEMS;

    EKG_mlp1<<<dim3(3, 64), 192>>>(Fc, W1, b1);
    EKG_mlp2<<<dim3(3, 72), 192>>>(W2, b2);
    EKG_softmax<<<B_SZ, CKK>>>(kw_tail, write_tail);

    dim3 grid(HH / ROWS_PER_BLOCK, N_IMG);
    EKG_conv_kernel<<<grid, 256>>>(Fd, out);
}